// round 2
// baseline (speedup 1.0000x reference)
#include <cuda_runtime.h>
#include <cstdint>

#define D 128
#define MAX_E 640000
#define MAX_N 40000

// ---- scratch (device globals; no allocation allowed) ----
__device__ __align__(16) float g_summed[MAX_N * D]; // segment_sum(messages)
__device__ __align__(16) float g_U[MAX_N * D];      // sum exp_s * m
__device__ __align__(16) float g_qk[MAX_N * D];     // per-node key-projected query
__device__ float g_qb[MAX_N];                        // per-node bias term
__device__ float g_sums[MAX_N];                      // sum exp_s
__device__ int   g_maxkey[MAX_N];                    // segment max (monotonic int key)
__device__ float g_scores[MAX_E];
__device__ __align__(16) float g_Mt[D * D];          // Mt[l*D+i] = (Wk Wq^T)[i][l]
__device__ __align__(16) float g_Wvo[D * D];         // (Wv Wo)[i][j] row-major
__device__ float g_c[D];                             // Wk bq
__device__ float g_w[D];                             // Wq bk
__device__ float g_bvo[D];                           // bv Wo
__device__ float g_beta[1];                          // bk . bq

__device__ __forceinline__ int float_key(float x) {
    int i = __float_as_int(x);
    return i >= 0 ? i : (i ^ 0x7fffffff);
}
__device__ __forceinline__ float key_float(int k) {
    return __int_as_float(k < 0 ? (k ^ 0x7fffffff) : k);
}

// ---- K0: fold weight matrices (tiny) ----
__global__ void k_precompute(const float* __restrict__ Wk, const float* __restrict__ bk,
                             const float* __restrict__ Wv, const float* __restrict__ bv,
                             const float* __restrict__ Wq, const float* __restrict__ bq,
                             const float* __restrict__ Wo) {
    int l = blockIdx.x;   // 0..127
    int t = threadIdx.x;  // 0..127
    if (blockIdx.y == 0) {
        // Mt[l*D + i] = sum_j Wk[i][j] * Wq[l][j]
        float acc = 0.f;
        for (int j = 0; j < D; j++) acc += Wk[t * D + j] * Wq[l * D + j];
        g_Mt[l * D + t] = acc;
        if (l == 0) {
            float c = 0.f, w = 0.f;
            for (int j = 0; j < D; j++) { c += Wk[t * D + j] * bq[j]; w += Wq[t * D + j] * bk[j]; }
            g_c[t] = c; g_w[t] = w;
            if (t == 0) { float b = 0.f; for (int j = 0; j < D; j++) b += bq[j] * bk[j]; g_beta[0] = b; }
        }
    } else {
        // Wvo[l][j] = sum_i Wv[l][i] * Wo[i][j]
        float acc = 0.f;
        for (int i = 0; i < D; i++) acc += Wv[l * D + i] * Wo[i * D + t];
        g_Wvo[l * D + t] = acc;
        if (l == 0) {
            float b = 0.f;
            for (int i = 0; i < D; i++) b += bv[i] * Wo[i * D + t];
            g_bvo[t] = b;
        }
    }
}

// ---- K1: init scratch (graph replays, must re-zero each launch) ----
__global__ void k_init(int N) {
    int i = blockIdx.x * blockDim.x + threadIdx.x;
    int tot = N * D;
    if (i < tot) {
        g_summed[i] = 0.f;
        g_U[i] = 0.f;
        if (i < N) { g_sums[i] = 0.f; g_maxkey[i] = (int)0x80000000; }
    }
}

// ---- K2: summed[r] += m[e]  (warp per edge, vector red) ----
__global__ void k_segsum(const float4* __restrict__ msg, const int* __restrict__ recv, int E) {
    int idx = blockIdx.x * blockDim.x + threadIdx.x;
    int e = idx >> 5, lane = idx & 31;
    if (e >= E) return;
    int r = __ldg(&recv[e]);
    float4 m = __ldg(&msg[e * 32 + lane]);
    float* dst = &g_summed[r * D + lane * 4];
    asm volatile("red.global.add.v4.f32 [%0], {%1,%2,%3,%4};"
                 :: "l"(dst), "f"(m.x), "f"(m.y), "f"(m.z), "f"(m.w) : "memory");
}

// ---- K2.5: qk[n] = Mt^T @ summed[n] + c ; qb[n] = w . summed[n] + beta ----
__global__ void k_qk(int N) {
    __shared__ float sh[8][D];
    int nb = blockIdx.x * 8;
    int t = threadIdx.x;
    #pragma unroll
    for (int k = 0; k < 8; k++) {
        int n = nb + k;
        sh[k][t] = (n < N) ? g_summed[n * D + t] : 0.f;
    }
    __syncthreads();
    float acc[8];
    float cc = g_c[t];
    #pragma unroll
    for (int k = 0; k < 8; k++) acc[k] = cc;
    for (int l = 0; l < D; l++) {
        float mv = g_Mt[l * D + t];
        #pragma unroll
        for (int k = 0; k < 8; k++) acc[k] += mv * sh[k][l];
    }
    #pragma unroll
    for (int k = 0; k < 8; k++) {
        int n = nb + k;
        if (n < N) g_qk[n * D + t] = acc[k];
    }
    if (t < 8) {
        int n = nb + t;
        if (n < N) {
            float q = g_beta[0];
            for (int l = 0; l < D; l++) q += g_w[l] * sh[t][l];
            g_qb[n] = q;
        }
    }
}

// ---- K3: scores[e] = (m[e].qk[r] + qb[r]) / sqrt(d); segment max ----
__global__ void k_scores(const float4* __restrict__ msg, const int* __restrict__ recv, int E) {
    int idx = blockIdx.x * blockDim.x + threadIdx.x;
    int e = idx >> 5, lane = idx & 31;
    if (e >= E) return;
    int r = __ldg(&recv[e]);
    float4 m = __ldg(&msg[e * 32 + lane]);
    const float4* qkp = reinterpret_cast<const float4*>(&g_qk[r * D]);
    float4 q = __ldg(&qkp[lane]);
    float dot = m.x * q.x + m.y * q.y + m.z * q.z + m.w * q.w;
    #pragma unroll
    for (int o = 16; o > 0; o >>= 1) dot += __shfl_xor_sync(0xffffffffu, dot, o);
    if (lane == 0) {
        float s = (dot + g_qb[r]) * 0.08838834764831845f; // 1/sqrt(128)
        g_scores[e] = s;
        atomicMax(&g_maxkey[r], float_key(s));
    }
}

// ---- K4: exp, segment sums of exp and exp*m (unnormalized) ----
__global__ void k_accum(const float4* __restrict__ msg, const int* __restrict__ recv, int E) {
    int idx = blockIdx.x * blockDim.x + threadIdx.x;
    int e = idx >> 5, lane = idx & 31;
    if (e >= E) return;
    int r = __ldg(&recv[e]);
    float s = g_scores[e];
    float mx = key_float(g_maxkey[r]);
    float w = __expf(s - mx);
    float4 m = __ldg(&msg[e * 32 + lane]);
    float* dst = &g_U[r * D + lane * 4];
    asm volatile("red.global.add.v4.f32 [%0], {%1,%2,%3,%4};"
                 :: "l"(dst), "f"(w * m.x), "f"(w * m.y), "f"(w * m.z), "f"(w * m.w) : "memory");
    if (lane == 0) atomicAdd(&g_sums[r], w);
}

// ---- K5: out[n] = (U[n]/den) @ Wvo + (sum/den)*bvo + bo ----
__global__ void k_out(const float* __restrict__ bo, float* __restrict__ out, int N) {
    __shared__ float sh[8][D];
    __shared__ float sa[8];
    int nb = blockIdx.x * 8;
    int t = threadIdx.x;
    #pragma unroll
    for (int k = 0; k < 8; k++) {
        int n = nb + k;
        float v = 0.f;
        float den = 1.f;
        if (n < N) {
            float se = g_sums[n];
            den = se + 1e-8f;
            v = g_U[n * D + t];
        }
        sh[k][t] = v / den;
        if (t == 0) sa[k] = (n < N) ? (g_sums[n] / den) : 0.f;
    }
    __syncthreads();
    float bj = __ldg(&bo[t]);
    float bvoj = g_bvo[t];
    float acc[8];
    #pragma unroll
    for (int k = 0; k < 8; k++) acc[k] = sa[k] * bvoj + bj;
    for (int l = 0; l < D; l++) {
        float wv = g_Wvo[l * D + t];
        #pragma unroll
        for (int k = 0; k < 8; k++) acc[k] += sh[k][l] * wv;
    }
    #pragma unroll
    for (int k = 0; k < 8; k++) {
        int n = nb + k;
        if (n < N) out[n * D + t] = acc[k];
    }
}

extern "C" void kernel_launch(void* const* d_in, const int* in_sizes, int n_in,
                              void* d_out, int out_size) {
    const float* messages = (const float*)d_in[0];
    const int*   receivers = (const int*)d_in[1];
    // num_segments may or may not appear as a 1-element buffer at index 2.
    int base = (n_in >= 11 && in_sizes[2] == 1) ? 3 : 2;
    const float* Wk = (const float*)d_in[base + 0];
    const float* bk = (const float*)d_in[base + 1];
    const float* Wv = (const float*)d_in[base + 2];
    const float* bv = (const float*)d_in[base + 3];
    const float* Wq = (const float*)d_in[base + 4];
    const float* bq = (const float*)d_in[base + 5];
    const float* Wo = (const float*)d_in[base + 6];
    const float* bo = (const float*)d_in[base + 7];

    int E = in_sizes[1];
    int N = out_size / D;
    float* out = (float*)d_out;

    k_precompute<<<dim3(D, 2), D>>>(Wk, bk, Wv, bv, Wq, bq, Wo);
    int tot = N * D;
    k_init<<<(tot + 255) / 256, 256>>>(N);
    long long ethreads = (long long)E * 32;
    int eblocks = (int)((ethreads + 255) / 256);
    k_segsum<<<eblocks, 256>>>((const float4*)messages, receivers, E);
    k_qk<<<(N + 7) / 8, D>>>(N);
    k_scores<<<eblocks, 256>>>((const float4*)messages, receivers, E);
    k_accum<<<eblocks, 256>>>((const float4*)messages, receivers, E);
    k_out<<<(N + 7) / 8, D>>>(bo, out, N);
}